// round 5
// baseline (speedup 1.0000x reference)
#include <cuda_runtime.h>
#include <cuda_bf16.h>

#define NN   100000
#define EE   1600000
#define CIN  1024
#define HD   64
#define ZDIM 32

#define SCAN_T 256
#define NBLK ((NN + SCAN_T - 1) / SCAN_T)   // 391

// ---------------- scratch (static __device__ — no allocation) ----------------
__device__ int   g_is64;
__device__ int   g_deg[NN];
__device__ int   g_off[NN];
__device__ int   g_cur[NN];
__device__ int   g_csr[EE];
__device__ float g_dinv[NN];
__device__ int   g_bsum[NBLK];
__device__ float g_t1[NN * HD];       // x @ Wg1 (fp32, 25.6 MB)
__device__ float g_t2[NN * ZDIM];     // h @ Wg2 (12.8 MB)
__device__ unsigned g_dzh[NN * 32];   // decoder hidden, bf16 hi (64 bf16 = 32 u32 / row)
__device__ unsigned g_dzl[NN * 32];   // decoder hidden, bf16 lo

// packed frag-layout weights: idx = ((kc*(N/8) + nb)*2 + j)*32 + lane
__device__ __align__(16) unsigned g_Wg1h[64 * 8 * 2 * 32];    // 32768
__device__ __align__(16) unsigned g_Wg1l[64 * 8 * 2 * 32];
__device__ __align__(16) unsigned g_Wf2h[4 * 128 * 2 * 32];   // 32768
__device__ __align__(16) unsigned g_Wf2l[4 * 128 * 2 * 32];

// ---------------- helpers ----------------
__device__ __forceinline__ void cvt_split(float x0, float x1, unsigned& hi, unsigned& lo) {
    __nv_bfloat162 h = __float22bfloat162_rn(make_float2(x0, x1));
    float2 hf = __bfloat1622float2(h);
    __nv_bfloat162 l = __float22bfloat162_rn(make_float2(x0 - hf.x, x1 - hf.y));
    hi = *reinterpret_cast<unsigned*>(&h);
    lo = *reinterpret_cast<unsigned*>(&l);
}

__device__ __forceinline__ void mma16816(float* c, const unsigned* a, unsigned b0, unsigned b1) {
    asm volatile(
        "mma.sync.aligned.m16n8k16.row.col.f32.bf16.bf16.f32 "
        "{%0,%1,%2,%3}, {%4,%5,%6,%7}, {%8,%9}, {%0,%1,%2,%3};\n"
        : "+f"(c[0]), "+f"(c[1]), "+f"(c[2]), "+f"(c[3])
        : "r"(a[0]), "r"(a[1]), "r"(a[2]), "r"(a[3]), "r"(b0), "r"(b1));
}

__device__ __forceinline__ void cp16(unsigned smem_addr, const void* gptr) {
    asm volatile("cp.async.ca.shared.global [%0], [%1], 16;\n"
                 :: "r"(smem_addr), "l"(gptr));
}
__device__ __forceinline__ void cp_commit() {
    asm volatile("cp.async.commit_group;\n");
}
__device__ __forceinline__ void cp_wait1() {
    asm volatile("cp.async.wait_group 1;\n");
}

// ---------------- edge dtype detection (int64 vs int32) ----------------
__global__ void detect_kernel(const int* __restrict__ ei32) {
    if (threadIdx.x == 0 && blockIdx.x == 0) {
        int nz = 0;
        for (int i = 0; i < 64; i++) nz |= (ei32[2 * i + 1] != 0);
        g_is64 = nz ? 0 : 1;
    }
}

__global__ void zero_deg_kernel() {
    int i = blockIdx.x * blockDim.x + threadIdx.x;
    if (i < NN) g_deg[i] = 0;
}

__global__ void hist_kernel(const void* __restrict__ ei) {
    int is64 = g_is64;
    int e = blockIdx.x * blockDim.x + threadIdx.x;
    if (e < EE) {
        int d = is64 ? (int)((const long long*)ei)[EE + e]
                     : ((const int*)ei)[EE + e];
        atomicAdd(&g_deg[d], 1);
    }
}

// ---------------- 2-level exclusive scan ----------------
__global__ void scan1_kernel() {
    __shared__ int s[SCAN_T];
    int t = threadIdx.x;
    int i = blockIdx.x * SCAN_T + t;
    s[t] = (i < NN) ? g_deg[i] : 0;
    __syncthreads();
    for (int o = SCAN_T / 2; o > 0; o >>= 1) {
        if (t < o) s[t] += s[t + o];
        __syncthreads();
    }
    if (t == 0) g_bsum[blockIdx.x] = s[0];
}

__global__ void scan2_kernel() {
    __shared__ int s[512];
    int t = threadIdx.x;
    int v = (t < NBLK) ? g_bsum[t] : 0;
    s[t] = v;
    __syncthreads();
    for (int o = 1; o < 512; o <<= 1) {
        int x = (t >= o) ? s[t - o] : 0;
        __syncthreads();
        s[t] += x;
        __syncthreads();
    }
    if (t < NBLK) g_bsum[t] = s[t] - v;
}

__global__ void scan3_kernel() {
    __shared__ int s[SCAN_T];
    int t = threadIdx.x;
    int i = blockIdx.x * SCAN_T + t;
    int v = (i < NN) ? g_deg[i] : 0;
    s[t] = v;
    __syncthreads();
    for (int o = 1; o < SCAN_T; o <<= 1) {
        int x = (t >= o) ? s[t - o] : 0;
        __syncthreads();
        s[t] += x;
        __syncthreads();
    }
    if (i < NN) {
        int off = g_bsum[blockIdx.x] + s[t] - v;
        g_off[i] = off;
        g_cur[i] = off;
        g_dinv[i] = rsqrtf((float)(v + 1));
    }
}

__global__ void scatter_kernel(const void* __restrict__ ei) {
    int is64 = g_is64;
    int e = blockIdx.x * blockDim.x + threadIdx.x;
    if (e < EE) {
        int s, d;
        if (is64) {
            s = (int)((const long long*)ei)[e];
            d = (int)((const long long*)ei)[EE + e];
        } else {
            s = ((const int*)ei)[e];
            d = ((const int*)ei)[EE + e];
        }
        int pos = atomicAdd(&g_cur[d], 1);
        g_csr[pos] = s;
    }
}

// ---------------- weight packing into frag layout ----------------
__global__ void pack_w_kernel(const float* __restrict__ W, int K, int N,
                              unsigned* __restrict__ ph, unsigned* __restrict__ pl) {
    int idx = blockIdx.x * blockDim.x + threadIdx.x;
    int total = (K / 16) * (N / 8) * 2 * 32;
    if (idx >= total) return;
    int lane = idx & 31;
    int j = (idx >> 5) & 1;
    int nb = (idx >> 6) % (N / 8);
    int kc = idx / (64 * (N / 8));
    int k0 = kc * 16 + (lane & 3) * 2 + j * 8;
    int n = nb * 8 + (lane >> 2);
    float w0 = W[(long long)k0 * N + n];
    float w1 = W[(long long)(k0 + 1) * N + n];
    cvt_split(w0, w1, ph[idx], pl[idx]);
}

// -------- GEMM1 (tensor core): t1[N,64] = x[N,1024] @ Wg1 (split-bf16 x3) --------
// B staged through a 3-stage cp.async smem pipeline; A prefetched 1 kc ahead.
__global__ __launch_bounds__(256, 3) void gemm1_mma_kernel(const float* __restrict__ x) {
    __shared__ __align__(16) unsigned Bs[3 * 1024];   // per stage: [0..511]=h, [512..1023]=l
    int tid = threadIdx.x;
    int wid = tid >> 5, lane = tid & 31;
    int gid = lane >> 2, tid4 = lane & 3;
    long long rowBase = (long long)blockIdx.x * 128 + wid * 16;

    long long r0 = rowBase + gid;
    long long r1 = r0 + 8;
    long long c0 = (r0 < NN) ? r0 : NN - 1;
    long long c1 = (r1 < NN) ? r1 : NN - 1;
    const float* p0 = x + c0 * CIN;
    const float* p1 = x + c1 * CIN;

    // per-thread fixed cp.async source/dest
    const unsigned* gsrc = (tid < 128) ? (g_Wg1h + tid * 4) : (g_Wg1l + (tid - 128) * 4);
    unsigned sdst = (tid < 128) ? (unsigned)(tid * 4) : (unsigned)(512 + (tid - 128) * 4);
    unsigned sbase = (unsigned)__cvta_generic_to_shared(Bs);

    // preload stages 0 and 1 (kc = 0, 1)
    cp16(sbase + (0 * 1024 + sdst) * 4, gsrc + 0 * 512);
    cp_commit();
    cp16(sbase + (1 * 1024 + sdst) * 4, gsrc + 1 * 512);
    cp_commit();

    float acc[8][4];
#pragma unroll
    for (int nb = 0; nb < 8; nb++)
#pragma unroll
        for (int q = 0; q < 4; q++) acc[nb][q] = 0.f;

    // A for kc = 0
    float2 a0, a1, a2, a3;
    {
        int col = tid4 * 2;
        a0 = *(const float2*)(p0 + col);
        a1 = *(const float2*)(p1 + col);
        a2 = *(const float2*)(p0 + col + 8);
        a3 = *(const float2*)(p1 + col + 8);
    }

    for (int kc = 0; kc < 64; kc++) {
        // A prefetch for kc+1
        float2 n0, n1, n2, n3;
        if (kc < 63) {
            int col = (kc + 1) * 16 + tid4 * 2;
            n0 = *(const float2*)(p0 + col);
            n1 = *(const float2*)(p1 + col);
            n2 = *(const float2*)(p0 + col + 8);
            n3 = *(const float2*)(p1 + col + 8);
        }

        cp_wait1();           // stage kc%3 ready
        __syncthreads();      // everyone done reading stage (kc-1)%3

        // B prefetch for kc+2 into stage (kc+2)%3  (== (kc-1)%3, safe after barrier)
        if (kc + 2 < 64)
            cp16(sbase + (((kc + 2) % 3) * 1024 + sdst) * 4, gsrc + (kc + 2) * 512);
        cp_commit();          // always commit: keeps wait_group(1) aligned

        unsigned ah[4], al[4];
        cvt_split(a0.x, a0.y, ah[0], al[0]);
        cvt_split(a1.x, a1.y, ah[1], al[1]);
        cvt_split(a2.x, a2.y, ah[2], al[2]);
        cvt_split(a3.x, a3.y, ah[3], al[3]);

        const unsigned* BsS = Bs + (kc % 3) * 1024;
#pragma unroll
        for (int nb = 0; nb < 8; nb++) {
            unsigned bh0 = BsS[nb * 64 + lane];
            unsigned bh1 = BsS[nb * 64 + 32 + lane];
            unsigned bl0 = BsS[512 + nb * 64 + lane];
            unsigned bl1 = BsS[512 + nb * 64 + 32 + lane];
            mma16816(acc[nb], ah, bh0, bh1);
            mma16816(acc[nb], al, bh0, bh1);
            mma16816(acc[nb], ah, bl0, bl1);
        }
        a0 = n0; a1 = n1; a2 = n2; a3 = n3;
    }

#pragma unroll
    for (int nb = 0; nb < 8; nb++) {
        int c = nb * 8 + tid4 * 2;
        if (r0 < NN)
            *(float2*)(g_t1 + r0 * HD + c) = make_float2(acc[nb][0], acc[nb][1]);
        if (r1 < NN)
            *(float2*)(g_t1 + r1 * HD + c) = make_float2(acc[nb][2], acc[nb][3]);
    }
}

// ------- gather1: aggregate(t1); h = relu(.+bg1); t2 = h@Wg2 -------
__global__ __launch_bounds__(256) void gather1_kernel(const float* __restrict__ bg1,
                                                      const float* __restrict__ Wg2) {
    __shared__ float Wg2s[HD * ZDIM];
    __shared__ float bg1s[HD];
    int tid = threadIdx.x;
    for (int i = tid; i < HD * ZDIM; i += 256) Wg2s[i] = Wg2[i];
    if (tid < HD) bg1s[tid] = bg1[tid];
    __syncthreads();

    int v = blockIdx.x * 8 + (tid >> 5);
    if (v >= NN) return;
    int lane = tid & 31;

    float a0a = 0.f, a0b = 0.f, a1a = 0.f, a1b = 0.f;
    int beg = g_off[v];
    int cnt = g_deg[v];
    for (int base = 0; base < cnt; base += 32) {
        int j = base + lane;
        int s = (j < cnt) ? g_csr[beg + j] : 0;
        float w = (j < cnt) ? g_dinv[s] : 0.f;
        int soff = s * HD;
        int rem = cnt - base;
#pragma unroll
        for (int qq = 0; qq < 4; qq++) {
            if (qq * 8 >= rem) break;
#pragma unroll
            for (int qi = 0; qi < 8; qi++) {
                int q = qq * 8 + qi;
                int   ov = __shfl_sync(0xffffffffu, soff, q);
                float wv = __shfl_sync(0xffffffffu, w, q);
                const float* p = g_t1 + ov;
                if (qi & 1) { a0b += wv * p[lane]; a1b += wv * p[lane + 32]; }
                else        { a0a += wv * p[lane]; a1a += wv * p[lane + 32]; }
            }
        }
    }
    float acc0 = a0a + a0b, acc1 = a1a + a1b;
    float di = g_dinv[v];
    const float* pv = g_t1 + (long long)v * HD;
    float h0 = fmaxf(di * acc0 + di * di * pv[lane]      + bg1s[lane],      0.f);
    float h1 = fmaxf(di * acc1 + di * di * pv[lane + 32] + bg1s[lane + 32], 0.f);

    float z = 0.f;
#pragma unroll
    for (int k = 0; k < 32; k++)
        z += __shfl_sync(0xffffffffu, h0, k) * Wg2s[k * ZDIM + lane];
#pragma unroll
    for (int k = 0; k < 32; k++)
        z += __shfl_sync(0xffffffffu, h1, k) * Wg2s[(32 + k) * ZDIM + lane];
    g_t2[v * ZDIM + lane] = z;
}

// -- gather2: z = aggregate(t2)+bg2; d = relu(z@Wf1+bf1); store d as bf16 hi/lo --
__global__ __launch_bounds__(256) void gather2_kernel(const float* __restrict__ bg2,
                                                      const float* __restrict__ Wf1,
                                                      const float* __restrict__ bf1) {
    __shared__ float Wf1s[ZDIM * HD];
    __shared__ float bg2s[ZDIM];
    __shared__ float bf1s[HD];
    int tid = threadIdx.x;
    for (int i = tid; i < ZDIM * HD; i += 256) Wf1s[i] = Wf1[i];
    if (tid < ZDIM) bg2s[tid] = bg2[tid];
    if (tid < HD)   bf1s[tid] = bf1[tid];
    __syncthreads();

    int v = blockIdx.x * 8 + (tid >> 5);
    if (v >= NN) return;
    int lane = tid & 31;

    float aa = 0.f, ab = 0.f;
    int beg = g_off[v];
    int cnt = g_deg[v];
    for (int base = 0; base < cnt; base += 32) {
        int j = base + lane;
        int s = (j < cnt) ? g_csr[beg + j] : 0;
        float w = (j < cnt) ? g_dinv[s] : 0.f;
        int soff = s * ZDIM;
        int rem = cnt - base;
#pragma unroll
        for (int qq = 0; qq < 4; qq++) {
            if (qq * 8 >= rem) break;
#pragma unroll
            for (int qi = 0; qi < 8; qi++) {
                int q = qq * 8 + qi;
                int   ov = __shfl_sync(0xffffffffu, soff, q);
                float wv = __shfl_sync(0xffffffffu, w, q);
                if (qi & 1) ab += wv * g_t2[ov + lane];
                else        aa += wv * g_t2[ov + lane];
            }
        }
    }
    float acc = aa + ab;
    float di = g_dinv[v];
    float z = di * acc + di * di * g_t2[(long long)v * ZDIM + lane] + bg2s[lane];

    float e0 = 0.f, e1 = 0.f;
#pragma unroll
    for (int k = 0; k < 32; k++) {
        float zk = __shfl_sync(0xffffffffu, z, k);
        e0 += zk * Wf1s[k * HD + lane];
        e1 += zk * Wf1s[k * HD + lane + 32];
    }
    float d0 = fmaxf(e0 + bf1s[lane],      0.f);
    float d1 = fmaxf(e1 + bf1s[lane + 32], 0.f);

    __nv_bfloat16* dzh = (__nv_bfloat16*)g_dzh;
    __nv_bfloat16* dzl = (__nv_bfloat16*)g_dzl;
    long long b = (long long)v * HD;
    __nv_bfloat16 h0 = __float2bfloat16_rn(d0);
    __nv_bfloat16 h1 = __float2bfloat16_rn(d1);
    dzh[b + lane]      = h0;
    dzh[b + lane + 32] = h1;
    dzl[b + lane]      = __float2bfloat16_rn(d0 - __bfloat162float(h0));
    dzl[b + lane + 32] = __float2bfloat16_rn(d1 - __bfloat162float(h1));
}

// ---- decode2 (tensor core): out = relu(d[N,64] @ Wf2[64,1024] + bf2) ----
// Block's full B slice (32 KB) staged to smem once; A prefetched 1 kc ahead.
__global__ __launch_bounds__(256, 3) void decode2_mma_kernel(const float* __restrict__ bf2,
                                                             float* __restrict__ out) {
    __shared__ __align__(16) unsigned BsH[4096];   // 16 KB: [kc][1024 u32] slice for this colBase
    __shared__ __align__(16) unsigned BsL[4096];   // 16 KB
    int tid = threadIdx.x;
    int wid = tid >> 5, lane = tid & 31;
    int gid = lane >> 2, tid4 = lane & 3;
    int warpM = wid & 3, warpN = wid >> 2;
    long long rowBase = (long long)blockIdx.x * 64 + warpM * 16;
    int colBase = blockIdx.y * 128 + warpN * 64;

    // stage B: per kc the block's 128-col slice is contiguous 1024 u32
    {
        const uint4* gh = (const uint4*)g_Wf2h;
        const uint4* gl = (const uint4*)g_Wf2l;
        uint4* sh = (uint4*)BsH;
        uint4* sl = (uint4*)BsL;
        int by = blockIdx.y;
#pragma unroll
        for (int jj = 0; jj < 4; jj++) {
            int j4 = tid + jj * 256;          // 0..1023
            int kc = j4 >> 8;
            int i4 = j4 & 255;
            sh[j4] = gh[kc * 2048 + by * 256 + i4];
            sl[j4] = gl[kc * 2048 + by * 256 + i4];
        }
    }

    long long r0 = rowBase + gid;
    long long r1 = r0 + 8;
    long long c0 = (r0 < NN) ? r0 : NN - 1;
    long long c1 = (r1 < NN) ? r1 : NN - 1;
    long long rp0 = c0 * 32, rp1 = c1 * 32;

    float acc[8][4];
#pragma unroll
    for (int nb = 0; nb < 8; nb++)
#pragma unroll
        for (int q = 0; q < 4; q++) acc[nb][q] = 0.f;

    // A for kc = 0
    unsigned ah[4], al[4];
    {
        long long o0 = rp0 + tid4;
        long long o1 = rp1 + tid4;
        ah[0] = g_dzh[o0];     al[0] = g_dzl[o0];
        ah[1] = g_dzh[o1];     al[1] = g_dzl[o1];
        ah[2] = g_dzh[o0 + 4]; al[2] = g_dzl[o0 + 4];
        ah[3] = g_dzh[o1 + 4]; al[3] = g_dzl[o1 + 4];
    }

    __syncthreads();

#pragma unroll
    for (int kc = 0; kc < 4; kc++) {
        unsigned nh[4], nl[4];
        if (kc < 3) {
            long long o0 = rp0 + (kc + 1) * 8 + tid4;
            long long o1 = rp1 + (kc + 1) * 8 + tid4;
            nh[0] = g_dzh[o0];     nl[0] = g_dzl[o0];
            nh[1] = g_dzh[o1];     nl[1] = g_dzl[o1];
            nh[2] = g_dzh[o0 + 4]; nl[2] = g_dzl[o0 + 4];
            nh[3] = g_dzh[o1 + 4]; nl[3] = g_dzl[o1 + 4];
        }
        const unsigned* bh = BsH + kc * 1024 + warpN * 512;
        const unsigned* bl = BsL + kc * 1024 + warpN * 512;
#pragma unroll
        for (int nb = 0; nb < 8; nb++) {
            unsigned bh0 = bh[nb * 64 + lane];
            unsigned bh1 = bh[nb * 64 + 32 + lane];
            unsigned bl0 = bl[nb * 64 + lane];
            unsigned bl1 = bl[nb * 64 + 32 + lane];
            mma16816(acc[nb], ah, bh0, bh1);
            mma16816(acc[nb], al, bh0, bh1);
            mma16816(acc[nb], ah, bl0, bl1);
        }
#pragma unroll
        for (int q = 0; q < 4; q++) { ah[q] = nh[q]; al[q] = nl[q]; }
    }

#pragma unroll
    for (int nb = 0; nb < 8; nb++) {
        int c = colBase + nb * 8 + tid4 * 2;
        float2 bv = *(const float2*)(bf2 + c);
        if (r0 < NN) {
            float2 o = make_float2(fmaxf(acc[nb][0] + bv.x, 0.f),
                                   fmaxf(acc[nb][1] + bv.y, 0.f));
            *(float2*)(out + r0 * CIN + c) = o;
        }
        if (r1 < NN) {
            float2 o = make_float2(fmaxf(acc[nb][2] + bv.x, 0.f),
                                   fmaxf(acc[nb][3] + bv.y, 0.f));
            *(float2*)(out + r1 * CIN + c) = o;
        }
    }
}

// ---------------------------------------------------------------------------
extern "C" void kernel_launch(void* const* d_in, const int* in_sizes, int n_in,
                              void* d_out, int out_size) {
    const float* x    = (const float*)d_in[0];
    const void*  ei   = d_in[1];
    const float* Wg1  = (const float*)d_in[2];
    const float* bg1  = (const float*)d_in[3];
    const float* Wg2  = (const float*)d_in[4];
    const float* bg2  = (const float*)d_in[5];
    const float* Wf1  = (const float*)d_in[6];
    const float* bf1  = (const float*)d_in[7];
    const float* Wf2  = (const float*)d_in[8];
    const float* bf2  = (const float*)d_in[9];
    float* out = (float*)d_out;

    unsigned* wg1h; cudaGetSymbolAddress((void**)&wg1h, g_Wg1h);
    unsigned* wg1l; cudaGetSymbolAddress((void**)&wg1l, g_Wg1l);
    unsigned* wf2h; cudaGetSymbolAddress((void**)&wf2h, g_Wf2h);
    unsigned* wf2l; cudaGetSymbolAddress((void**)&wf2l, g_Wf2l);

    // Order chosen so the 4th launch (the one ncu profiles) is gemm1_mma.
    detect_kernel<<<1, 32>>>((const int*)ei);                       // 1
    zero_deg_kernel<<<NBLK, SCAN_T>>>();                            // 2
    pack_w_kernel<<<128, 256>>>(Wg1, CIN, HD, wg1h, wg1l);          // 3
    gemm1_mma_kernel<<<(NN + 127) / 128, 256>>>(x);                 // 4 <- profiled

    hist_kernel<<<EE / 256, 256>>>(ei);
    scan1_kernel<<<NBLK, SCAN_T>>>();
    scan2_kernel<<<1, 512>>>();
    scan3_kernel<<<NBLK, SCAN_T>>>();
    scatter_kernel<<<EE / 256, 256>>>(ei);
    pack_w_kernel<<<128, 256>>>(Wf2, HD, CIN, wf2h, wf2l);

    gather1_kernel<<<(NN + 7) / 8, 256>>>(bg1, Wg2);
    gather2_kernel<<<(NN + 7) / 8, 256>>>(bg2, Wf1, bf1);

    dim3 g2((NN + 63) / 64, CIN / 128);
    decode2_mma_kernel<<<g2, 256>>>(bf2, out);
}